// round 3
// baseline (speedup 1.0000x reference)
#include <cuda_runtime.h>

// MinConv2d: 3x3 min-pool, stride 1, pad 1 (zero padding PARTICIPATES in min).
// Input/output: (8, 64, 512, 512) fp32 -> 512 planes of 512x512.
//
// R2: ILP=2 across planes. Each block handles TWO planes with two independent
// rolling separable-min pipelines per thread, doubling in-flight DRAM loads
// per warp (MLP). Row tile enlarged to 64 to amortize prologue and halve
// tile-boundary re-reads.

#define PLANE_H 512
#define PLANE_W 512
#define PLANE_ELEMS (PLANE_H * PLANE_W)
#define ROWS_PER_BLOCK 64
#define THREADS 128   // 128 * 4 floats = 512 = full row width

__device__ __forceinline__ float4 fmin4(float4 a, float4 b) {
    return make_float4(fminf(a.x, b.x), fminf(a.y, b.y),
                       fminf(a.z, b.z), fminf(a.w, b.w));
}

__global__ __launch_bounds__(THREADS)
void minpool3x3_kernel(const float* __restrict__ x, float* __restrict__ out) {
    const int p0 = blockIdx.y * 2;   // two planes per block
    const float* __restrict__ xa = x   + (size_t)p0 * PLANE_ELEMS;
    const float* __restrict__ xb = xa  + PLANE_ELEMS;
    float* __restrict__ oa       = out + (size_t)p0 * PLANE_ELEMS;
    float* __restrict__ ob       = oa  + PLANE_ELEMS;

    const int base   = threadIdx.x * 4;          // column offset of strip
    const int y0     = blockIdx.x * ROWS_PER_BLOCK;
    const bool hasL  = (base != 0);
    const bool hasR  = (base + 4 != PLANE_W);

    float4 a2, a1;   // rolling horizontal mins, plane A
    float4 b2, b1;   // rolling horizontal mins, plane B

    #pragma unroll 2
    for (int r = -1; r <= ROWS_PER_BLOCK; ++r) {
        const int yi = y0 + r;
        float4 ha, hb;
        if (yi < 0 || yi >= PLANE_H) {
            // Padded row: zeros -> horizontal min is 0 everywhere.
            ha = make_float4(0.f, 0.f, 0.f, 0.f);
            hb = ha;
        } else {
            const size_t roff = (size_t)yi * PLANE_W + base;
            const float* ra = xa + roff;
            const float* rb = xb + roff;
            // Issue both vector loads (and edge scalars) before any math:
            // two independent DRAM streams per thread.
            const float4 va = *reinterpret_cast<const float4*>(ra);
            const float4 vb = *reinterpret_cast<const float4*>(rb);
            const float laL = hasL ? __ldg(ra - 1) : 0.0f;
            const float laR = hasR ? __ldg(ra + 4) : 0.0f;
            const float lbL = hasL ? __ldg(rb - 1) : 0.0f;
            const float lbR = hasR ? __ldg(rb + 4) : 0.0f;

            ha.x = fminf(laL,  fminf(va.x, va.y));
            ha.y = fminf(va.x, fminf(va.y, va.z));
            ha.z = fminf(va.y, fminf(va.z, va.w));
            ha.w = fminf(va.z, fminf(va.w, laR));

            hb.x = fminf(lbL,  fminf(vb.x, vb.y));
            hb.y = fminf(vb.x, fminf(vb.y, vb.z));
            hb.z = fminf(vb.y, fminf(vb.z, vb.w));
            hb.w = fminf(vb.z, fminf(vb.w, lbR));
        }

        if (r >= 1) {
            const size_t ooff = (size_t)(yi - 1) * PLANE_W + base;
            *reinterpret_cast<float4*>(oa + ooff) = fmin4(a2, fmin4(a1, ha));
            *reinterpret_cast<float4*>(ob + ooff) = fmin4(b2, fmin4(b1, hb));
        }
        a2 = a1; a1 = ha;
        b2 = b1; b1 = hb;
    }
}

extern "C" void kernel_launch(void* const* d_in, const int* in_sizes, int n_in,
                              void* d_out, int out_size) {
    const float* x = (const float*)d_in[0];
    float* out = (float*)d_out;

    const int plane_pairs = (8 * 64) / 2;                 // 256
    dim3 grid(PLANE_H / ROWS_PER_BLOCK, plane_pairs);     // (8, 256)
    dim3 block(THREADS);
    minpool3x3_kernel<<<grid, block>>>(x, out);
}

// round 5
// speedup vs baseline: 1.1864x; 1.1864x over previous
#include <cuda_runtime.h>

// MinConv2d: 3x3 min-pool, stride 1, pad 1 (zero padding PARTICIPATES in min).
// Input/output: (8, 64, 512, 512) fp32 -> 512 planes of 512x512.
//
// R3: R1 structure (1 plane/block, separable rolling min) + unconditional
// clamped-row loads batched 4 rows at a time so ptxas front-hoists 4
// independent float4 DRAM loads per thread (MLP_p1 ~12). Zero padding is
// applied as a predicated select AFTER the load, never as a branch around it.

#define PLANE_H 512
#define PLANE_W 512
#define ROWS_PER_BLOCK 32
#define THREADS 128   // 128 * 4 floats = 512 = full row width

__device__ __forceinline__ float4 fmin4(float4 a, float4 b) {
    return make_float4(fminf(a.x, b.x), fminf(a.y, b.y),
                       fminf(a.z, b.z), fminf(a.w, b.w));
}

// Horizontal 3-min of a row strip (v with left/right neighbor scalars),
// zeroed if the row is a padded row.
__device__ __forceinline__ float4 hmin_row(float4 v, float l, float r, bool valid) {
    float4 h;
    h.x = fminf(l,   fminf(v.x, v.y));
    h.y = fminf(v.x, fminf(v.y, v.z));
    h.z = fminf(v.y, fminf(v.z, v.w));
    h.w = fminf(v.z, fminf(v.w, r));
    if (!valid) h = make_float4(0.f, 0.f, 0.f, 0.f);
    return h;
}

__global__ __launch_bounds__(THREADS)
void minpool3x3_kernel(const float* __restrict__ x, float* __restrict__ out) {
    const int plane = blockIdx.y;
    const float* __restrict__ xp = x + (size_t)plane * PLANE_H * PLANE_W;
    float* __restrict__ op = out + (size_t)plane * PLANE_H * PLANE_W;

    const int base  = threadIdx.x * 4;
    const int y0    = blockIdx.x * ROWS_PER_BLOCK;
    const bool hasL = (base != 0);
    const bool hasR = (base + 4 != PLANE_W);

    // ---- prologue: input rows y0-1 and y0 (may be padded) ----
    float4 h2, h1;
    {
        int yi = y0 - 1;
        int yc = yi < 0 ? 0 : yi;                    // clamped, always legal
        const float* row = xp + (size_t)yc * PLANE_W + base;
        float4 v  = *reinterpret_cast<const float4*>(row);
        float  l  = hasL ? __ldg(row - 1) : 0.0f;
        float  r  = hasR ? __ldg(row + 4) : 0.0f;
        h2 = hmin_row(v, l, r, yi >= 0);
    }
    {
        const float* row = xp + (size_t)y0 * PLANE_W + base;
        float4 v  = *reinterpret_cast<const float4*>(row);
        float  l  = hasL ? __ldg(row - 1) : 0.0f;
        float  r  = hasR ? __ldg(row + 4) : 0.0f;
        h1 = hmin_row(v, l, r, true);
    }

    // ---- steady state: 32 input rows y0+1 .. y0+32, batched 4 at a time ----
    for (int r0 = 1; r0 <= ROWS_PER_BLOCK; r0 += 4) {
        float4 v[4];
        float  L[4], R[4];
        bool   val[4];

        #pragma unroll
        for (int j = 0; j < 4; ++j) {
            const int yi = y0 + r0 + j;              // >= 1, may be 512 (padded)
            const int yc = yi < PLANE_H ? yi : PLANE_H - 1;   // clamp: load legal
            const float* row = xp + (size_t)yc * PLANE_W + base;
            v[j]   = *reinterpret_cast<const float4*>(row);
            L[j]   = hasL ? __ldg(row - 1) : 0.0f;
            R[j]   = hasR ? __ldg(row + 4) : 0.0f;
            val[j] = yi < PLANE_H;
        }

        #pragma unroll
        for (int j = 0; j < 4; ++j) {
            const float4 h = hmin_row(v[j], L[j], R[j], val[j]);
            const int yo = y0 + r0 + j - 1;          // output row completed
            *reinterpret_cast<float4*>(op + (size_t)yo * PLANE_W + base) =
                fmin4(h2, fmin4(h1, h));
            h2 = h1;
            h1 = h;
        }
    }
}

extern "C" void kernel_launch(void* const* d_in, const int* in_sizes, int n_in,
                              void* d_out, int out_size) {
    const float* x = (const float*)d_in[0];
    float* out = (float*)d_out;

    const int planes = 8 * 64;                       // 512
    dim3 grid(PLANE_H / ROWS_PER_BLOCK, planes);     // (16, 512)
    dim3 block(THREADS);
    minpool3x3_kernel<<<grid, block>>>(x, out);
}